// round 5
// baseline (speedup 1.0000x reference)
#include <cuda_runtime.h>

#define BATCH 2048
#define MF    26
#define KE    32
#define C1    (MF*MF)       // 676
#define NPAIR 351
#define NTRI  3276
#define NJ    3328          // 26*128
#define OUTW  256
#define FSTR  3712          // F row: [G 0..350 | 32@351 | T 352..3627 | sx 3628..3653 | 32@3654 | 0..3711]

typedef unsigned long long ull;

__device__ int   g_e2pqj[NTRI];          // p | q<<8 | j<<16
__device__ float g_W1s[352 * 128];       // [pq][i]; row 351 = b1
__device__ float g_W2t[NJ * 128];        // [c=i*26+j][h] == [i][j*128+h] with i-stride NJ
__device__ float g_U[352 * NJ];          // [pq][j*128+h]; row 351 = v[j][h]
__device__ float g_Up[NJ * 128];         // rows: 0..3275 fold, 3276..3301 v, 3302 b2, rest 0
__device__ float g_F[BATCH * FSTR];

#define FMA2(a, x, y) asm("fma.rn.f32x2 %0, %1, %2, %0;" : "+l"(a) : "l"(x), "l"(y))
#define MUL2(d, x, y) asm("mul.rn.f32x2 %0, %1, %2;" : "=l"(d) : "l"(x), "l"(y))
#define ADD2(a, x)    asm("add.rn.f32x2 %0, %0, %1;" : "+l"(a) : "l"(x))
#define DUP2(d, f)    asm("mov.b64 %0, {%1, %1};" : "=l"(d) : "f"(f))

__device__ __forceinline__ int pq_off(int p) { return p * MF - (p * (p - 1)) / 2; }

__device__ __forceinline__ void pq_decode(int pq, int& p, int& q) {
    p = (int)(26.5f - sqrtf(702.25f - 2.0f * (float)pq));
    if (p < 0) p = 0;
    while (p > 0 && pq_off(p) > pq) p--;
    while (pq_off(p + 1) <= pq) p++;
    q = p + (pq - pq_off(p));
}

// ---------------------------------------------------------------------------
// kA_prep: [0,416)   W2 transpose 32x32 tiles -> g_W2t
//          [416,592) W1s build (row 351 = b1)
//          [592,605) e2pqj table
// ---------------------------------------------------------------------------
__global__ __launch_bounds__(256) void kA_prep(
    const float* __restrict__ W1, const float* __restrict__ b1,
    const float* __restrict__ W2)
{
    const int bx = blockIdx.x;
    const int t  = threadIdx.x;
    if (bx < 416) {
        __shared__ float tile[32][33];
        int c0 = (bx % 104) * 32;
        int h0 = (bx / 104) * 32;
        int tx = t & 31, ty = t >> 5;
#pragma unroll
        for (int r = 0; r < 4; r++)
            tile[ty + 8 * r][tx] = W2[(size_t)(h0 + ty + 8 * r) * NJ + c0 + tx];
        __syncthreads();
#pragma unroll
        for (int r = 0; r < 4; r++)
            g_W2t[(size_t)(c0 + ty + 8 * r) * 128 + h0 + tx] = tile[tx][ty + 8 * r];
    } else if (bx < 592) {
        int idx = (bx - 416) * 256 + t;           // 352*128
        int pq = idx >> 7, i = idx & 127;
        float v;
        if (pq == NPAIR) v = b1[i];
        else {
            int p, q; pq_decode(pq, p, q);
            v = W1[i * C1 + p * MF + q];
            if (p < q) v += W1[i * C1 + q * MF + p];
        }
        g_W1s[idx] = v;
    } else {
        int e = (bx - 592) * 256 + t;
        if (e < NTRI) {
            int rem = e, p = 0;
            while (rem >= (MF - p) * (MF - p + 1) / 2) { rem -= (MF - p) * (MF - p + 1) / 2; p++; }
            int q = p;
            while (rem >= MF - q) { rem -= MF - q; q++; }
            g_e2pqj[e] = p | (q << 8) | ((q + rem) << 16);
        }
    }
}

// ---------------------------------------------------------------------------
// k_u: U[m][n] = sum_i W1s[m][i] * W2t[i][n].  GEMM M=352 N=3328 K=128.
//   Tile 32m x 128n, 256 thr, 4m x 4n per thread, grid (11, 26).
// ---------------------------------------------------------------------------
__global__ __launch_bounds__(256) void k_u() {
    __shared__ float As[32][36];     // [kk][m]
    __shared__ float Bs[32][132];    // [kk][n]
    const int t = threadIdx.x;
    const int tx = t & 31;    // n = 4*tx
    const int ty = t >> 5;    // m = 4*ty
    const int m0 = blockIdx.x * 32;
    const int n0 = blockIdx.y * 128;

    ull acc[4][2];
#pragma unroll
    for (int r = 0; r < 4; r++) { acc[r][0] = 0ULL; acc[r][1] = 0ULL; }

    for (int kc = 0; kc < 128; kc += 32) {
        __syncthreads();
        {   // A tile transpose: 32m x 32k
            int row = t >> 3, c4 = t & 7;
            float4 v = *reinterpret_cast<const float4*>(
                g_W1s + (size_t)(m0 + row) * 128 + kc + 4 * c4);
            As[4 * c4 + 0][row] = v.x;
            As[4 * c4 + 1][row] = v.y;
            As[4 * c4 + 2][row] = v.z;
            As[4 * c4 + 3][row] = v.w;
        }
#pragma unroll
        for (int l = 0; l < 4; l++) {   // B: 32k x 128n, i-row stride is NJ
            int idx = t + 256 * l;
            int row = idx >> 5, c4 = idx & 31;
            *reinterpret_cast<float4*>(&Bs[row][4 * c4]) =
                *reinterpret_cast<const float4*>(g_W2t + (size_t)(kc + row) * NJ + n0 + 4 * c4);
        }
        __syncthreads();

#pragma unroll
        for (int kk = 0; kk < 32; kk++) {
            float4 a = *reinterpret_cast<const float4*>(&As[kk][4 * ty]);
            ulonglong2 w = *reinterpret_cast<const ulonglong2*>(&Bs[kk][4 * tx]);
            ull d;
            DUP2(d, a.x); FMA2(acc[0][0], w.x, d); FMA2(acc[0][1], w.y, d);
            DUP2(d, a.y); FMA2(acc[1][0], w.x, d); FMA2(acc[1][1], w.y, d);
            DUP2(d, a.z); FMA2(acc[2][0], w.x, d); FMA2(acc[2][1], w.y, d);
            DUP2(d, a.w); FMA2(acc[3][0], w.x, d); FMA2(acc[3][1], w.y, d);
        }
    }
#pragma unroll
    for (int r = 0; r < 4; r++) {
        float* dst = g_U + (size_t)(m0 + 4 * ty + r) * NJ + n0 + 4 * tx;
        *reinterpret_cast<float2*>(dst)     = *reinterpret_cast<float2*>(&acc[r][0]);
        *reinterpret_cast<float2*>(dst + 2) = *reinterpret_cast<float2*>(&acc[r][1]);
    }
}

// ---------------------------------------------------------------------------
// k_fold: Up rows: e<3276 permutation fold of U; 3276..3301 = U row 351 (v);
//         3302 = b2; 3303..3327 = 0.
// ---------------------------------------------------------------------------
__global__ void k_fold(const float* __restrict__ b2) {
    int gid = blockIdx.x * blockDim.x + threadIdx.x;   // 3328*128
    int e = gid >> 7, h = gid & 127;
    float val = 0.f;
    if (e < NTRI) {
        int c = g_e2pqj[e];
        int p = c & 255, q = (c >> 8) & 255, j = (c >> 16) & 255;
        #define CU(PQ, J) g_U[(size_t)(PQ) * NJ + (J) * 128 + h]
        if (p < q) {
            if (q < j) val = CU(pq_off(p) + q - p, j) + CU(pq_off(p) + j - p, q) + CU(pq_off(q) + j - q, p);
            else       val = CU(pq_off(p) + q - p, q) + CU(pq_off(q), p);
        } else {
            if (q < j) val = CU(pq_off(p), j) + CU(pq_off(p) + j - p, p);
            else       val = CU(pq_off(p), p);
        }
        #undef CU
    } else if (e < NTRI + MF) {
        val = g_U[(size_t)NPAIR * NJ + (e - NTRI) * 128 + h];   // v[j][h]
    } else if (e == NTRI + MF) {
        val = b2[h];
    }
    g_Up[(size_t)e * 128 + h] = val;
}

// ---------------------------------------------------------------------------
// k_feat: per-batch features. Block = 1 b, 384 threads.
// ---------------------------------------------------------------------------
__global__ __launch_bounds__(384) void k_feat(const float* __restrict__ x0g) {
    __shared__ ull xsr[MF][18];
    const int b = blockIdx.x;
    const int t = threadIdx.x;

    for (int idx = t; idx < MF * 16; idx += 384) {
        int j = idx >> 4, kp = idx & 15;
        xsr[j][kp] = *reinterpret_cast<const ull*>(x0g + (size_t)b * MF * KE + j * KE + 2 * kp);
    }
    __syncthreads();

    float* F = g_F + (size_t)b * FSTR;

    if (t == 0) { F[351] = 32.0f; F[3654] = 32.0f; }
    if (t < 57) F[3655 + t] = 0.f;

    if (t < MF) {   // sx
        ull s0 = 0, s1 = 0;
#pragma unroll
        for (int cc = 0; cc < 8; cc++) {
            ulonglong2 v = *reinterpret_cast<const ulonglong2*>(&xsr[t][2 * cc]);
            ADD2(s0, v.x); ADD2(s1, v.y);
        }
        ADD2(s0, s1);
        float2 sf = *reinterpret_cast<float2*>(&s0);
        F[3628 + t] = sf.x + sf.y;
    }

    // T entries (+ G at run starts)
    int e0 = t * 9;
    int e1 = e0 + 9; if (e1 > NTRI) e1 = NTRI;
    int curpq = -1;
    ull xx[16];
    for (int e = e0; e < e1; e++) {
        int c = g_e2pqj[e];
        int p = c & 255, q = (c >> 8) & 255, j = (c >> 16) & 255;
        if ((c & 0xFFFF) != curpq) {
            curpq = c & 0xFFFF;
#pragma unroll
            for (int cc = 0; cc < 8; cc++) {
                ulonglong2 ap = *reinterpret_cast<const ulonglong2*>(&xsr[p][2 * cc]);
                ulonglong2 aq = *reinterpret_cast<const ulonglong2*>(&xsr[q][2 * cc]);
                MUL2(xx[2 * cc],     ap.x, aq.x);
                MUL2(xx[2 * cc + 1], ap.y, aq.y);
            }
        }
        ull a0 = 0, a1 = 0, a2 = 0, a3 = 0;
#pragma unroll
        for (int cc = 0; cc < 8; cc++) {
            ulonglong2 xj = *reinterpret_cast<const ulonglong2*>(&xsr[j][2 * cc]);
            if (cc & 1) { FMA2(a2, xx[2 * cc], xj.x); FMA2(a3, xx[2 * cc + 1], xj.y); }
            else        { FMA2(a0, xx[2 * cc], xj.x); FMA2(a1, xx[2 * cc + 1], xj.y); }
        }
        ADD2(a0, a1); ADD2(a2, a3); ADD2(a0, a2);
        float2 af = *reinterpret_cast<float2*>(&a0);
        F[352 + e] = af.x + af.y;

        if (j == q) {   // first entry of this pq run -> emit G[pq]
            ull g0 = 0, g1 = 0;
#pragma unroll
            for (int kp = 0; kp < 16; kp += 2) { ADD2(g0, xx[kp]); ADD2(g1, xx[kp + 1]); }
            ADD2(g0, g1);
            float2 gf = *reinterpret_cast<float2*>(&g0);
            F[pq_off(p) + (q - p)] = gf.x + gf.y;
        }
    }
}

// ---------------------------------------------------------------------------
// k_gemm: out[b][ocol + hw + hloc] = sum_k F[b][fcol+k] * W[k*128 + hw + hloc]
//   Tile 32b x 64h, full k, 256 thr, per-thread 8b (4 f32x2 b-pairs) x 1h.
// ---------------------------------------------------------------------------
__global__ __launch_bounds__(256) void k_gemm(int sel, float* __restrict__ out) {
    __shared__ ull   As2[32][18];   // [kk][b-pair]
    __shared__ float Ws[32][68];

    const float* W  = sel ? g_Up : g_W1s;
    const int klen  = sel ? 3328 : 352;
    const int fcol  = sel ? 352 : 0;
    const int ocol  = sel ? 128 : 0;

    const int t    = threadIdx.x;
    const int hloc = t & 63;
    const int bg   = t >> 6;          // 4 groups of 8 b
    const int b0   = blockIdx.x * 32;
    const int hw   = blockIdx.y * 64;

    ull acc[4] = {0ULL, 0ULL, 0ULL, 0ULL};

    const int arow = t >> 3, ac4 = t & 7;
    const int abp = arow >> 1, alo = arow & 1;

    for (int kc = 0; kc < klen; kc += 32) {
        __syncthreads();
        {   // A tile: 32b x 32k, pair-packed transpose
            float4 v = *reinterpret_cast<const float4*>(
                g_F + (size_t)(b0 + arow) * FSTR + fcol + kc + 4 * ac4);
            reinterpret_cast<float*>(&As2[4 * ac4 + 0][abp])[alo] = v.x;
            reinterpret_cast<float*>(&As2[4 * ac4 + 1][abp])[alo] = v.y;
            reinterpret_cast<float*>(&As2[4 * ac4 + 2][abp])[alo] = v.z;
            reinterpret_cast<float*>(&As2[4 * ac4 + 3][abp])[alo] = v.w;
        }
#pragma unroll
        for (int l = 0; l < 2; l++) {   // W tile: 32k x 64h direct rows
            int idx = t + 256 * l;
            int row = idx >> 4, c4 = idx & 15;
            *reinterpret_cast<float4*>(&Ws[row][4 * c4]) =
                *reinterpret_cast<const float4*>(W + (size_t)(kc + row) * 128 + hw + 4 * c4);
        }
        __syncthreads();

#pragma unroll
        for (int kk = 0; kk < 32; kk++) {
            ulonglong2 a01 = *reinterpret_cast<const ulonglong2*>(&As2[kk][4 * bg]);
            ulonglong2 a23 = *reinterpret_cast<const ulonglong2*>(&As2[kk][4 * bg + 2]);
            ull wd; DUP2(wd, Ws[kk][hloc]);
            FMA2(acc[0], a01.x, wd);
            FMA2(acc[1], a01.y, wd);
            FMA2(acc[2], a23.x, wd);
            FMA2(acc[3], a23.y, wd);
        }
    }

#pragma unroll
    for (int i = 0; i < 4; i++) {
        float2 v = *reinterpret_cast<float2*>(&acc[i]);
        int b = b0 + 8 * bg + 2 * i;
        out[(size_t)b * OUTW + ocol + hw + hloc]       = v.x;
        out[(size_t)(b + 1) * OUTW + ocol + hw + hloc] = v.y;
    }
}

// ---------------------------------------------------------------------------
extern "C" void kernel_launch(void* const* d_in, const int* in_sizes, int n_in,
                              void* d_out, int out_size) {
    const float* inputs = (const float*)d_in[0];  // [2048,26,32]
    const float* W1     = (const float*)d_in[1];  // [128,26,26]
    const float* b1     = (const float*)d_in[2];  // [128]
    const float* W2     = (const float*)d_in[3];  // [128,128,26]
    const float* b2     = (const float*)d_in[4];  // [128]
    float* out = (float*)d_out;                   // [2048,256]

    kA_prep<<<605, 256>>>(W1, b1, W2);
    k_u<<<dim3(11, 26), 256>>>();
    k_fold<<<(NJ * 128) / 256, 256>>>(b2);
    k_feat<<<BATCH, 384>>>(inputs);
    k_gemm<<<dim3(BATCH / 32, 2), 256>>>(0, out);
    k_gemm<<<dim3(BATCH / 32, 2), 256>>>(1, out);
}

// round 6
// speedup vs baseline: 1.6828x; 1.6828x over previous
#include <cuda_runtime.h>

#define BATCH 2048
#define MF    26
#define KE    32
#define C1    (MF*MF)       // 676
#define NPAIR 351
#define NTRI  3276
#define NJ    3328          // 26*128
#define OUTW  256
#define FSTR  3712          // F row: [G 0..350 | 32@351 | T 352..3627 | sx 3628..3653 | 32@3654 | 0..3711]
#define FEATB 1024          // feat blocks in kB

typedef unsigned long long ull;

__device__ int   g_e2pqj[NTRI];          // p | q<<8 | j<<16
__device__ int   g_meta[384];            // p | q<<5 | runbase<<10  (0 for pq>=351)
__device__ float g_W1s[384 * 128];       // [pq][i]; row 351 = b1, rows 352..383 = 0
__device__ float g_W2t[NJ * 128];        // [i][j*128+h], i-row stride NJ
__device__ float g_U[352 * NJ];          // [pq][j*128+h]; row 351 = v[j][h]
__device__ float g_Up[NJ * 128];         // rows: 0..3275 fold, 3276..3301 v, 3302 b2, rest 0
__device__ float g_F[BATCH * FSTR];
__device__ float g_P[4 * BATCH * 128];   // gemm1 k-split partials

#define FMA2(a, x, y) asm("fma.rn.f32x2 %0, %1, %2, %0;" : "+l"(a) : "l"(x), "l"(y))
#define MUL2(d, x, y) asm("mul.rn.f32x2 %0, %1, %2;" : "=l"(d) : "l"(x), "l"(y))
#define ADD2(a, x)    asm("add.rn.f32x2 %0, %0, %1;" : "+l"(a) : "l"(x))
#define DUP2(d, f)    asm("mov.b64 %0, {%1, %1};" : "=l"(d) : "f"(f))

__device__ __forceinline__ int pq_off(int p) { return p * MF - (p * (p - 1)) / 2; }

__device__ __forceinline__ void pq_decode(int pq, int& p, int& q) {
    p = (int)(26.5f - sqrtf(702.25f - 2.0f * (float)pq));
    if (p < 0) p = 0;
    while (p > 0 && pq_off(p) > pq) p--;
    while (pq_off(p + 1) <= pq) p++;
    q = p + (pq - pq_off(p));
}

__device__ __forceinline__ float hadd2(ull a) {
    float2 f = *reinterpret_cast<float2*>(&a);
    return f.x + f.y;
}

// ---------------------------------------------------------------------------
// kA_prep: [0,416)    W2 transpose -> g_W2t
//          [416,608)  W1s build, 384 rows (351=b1, >=352 zero)
//          [608,621)  e2pqj table
//          [621]      meta table (p,q,runbase)
// ---------------------------------------------------------------------------
__global__ __launch_bounds__(256) void kA_prep(
    const float* __restrict__ W1, const float* __restrict__ b1,
    const float* __restrict__ W2)
{
    const int bx = blockIdx.x;
    const int t  = threadIdx.x;
    if (bx < 416) {
        __shared__ float tile[32][33];
        int c0 = (bx % 104) * 32;
        int h0 = (bx / 104) * 32;
        int tx = t & 31, ty = t >> 5;
#pragma unroll
        for (int r = 0; r < 4; r++)
            tile[ty + 8 * r][tx] = W2[(size_t)(h0 + ty + 8 * r) * NJ + c0 + tx];
        __syncthreads();
#pragma unroll
        for (int r = 0; r < 4; r++)
            g_W2t[(size_t)(c0 + ty + 8 * r) * 128 + h0 + tx] = tile[tx][ty + 8 * r];
    } else if (bx < 608) {
        int idx = (bx - 416) * 256 + t;           // 384*128
        int pq = idx >> 7, i = idx & 127;
        float v = 0.f;
        if (pq == NPAIR) v = b1[i];
        else if (pq < NPAIR) {
            int p, q; pq_decode(pq, p, q);
            v = W1[i * C1 + p * MF + q];
            if (p < q) v += W1[i * C1 + q * MF + p];
        }
        g_W1s[idx] = v;
    } else if (bx < 621) {
        int e = (bx - 608) * 256 + t;
        if (e < NTRI) {
            int rem = e, p = 0;
            while (rem >= (MF - p) * (MF - p + 1) / 2) { rem -= (MF - p) * (MF - p + 1) / 2; p++; }
            int q = p;
            while (rem >= MF - q) { rem -= MF - q; q++; }
            g_e2pqj[e] = p | (q << 8) | ((q + rem) << 16);
        }
    } else {
        for (int idx = t; idx < 384; idx += 256) {
            int v = 0;
            if (idx < NPAIR) {
                int p, q; pq_decode(idx, p, q);
                int rb = 0;
                for (int pp = 0; pp < p; pp++) rb += (MF - pp) * (MF - pp + 1) / 2;
                rb += (MF - p) * (MF - p + 1) / 2 - (MF - q) * (MF - q + 1) / 2;
                v = p | (q << 5) | (rb << 10);
            }
            g_meta[idx] = v;
        }
    }
}

// ---------------------------------------------------------------------------
// kB: blocks [0,1024)  feat: 2 batches/block, 384 thr, 12 warps (6/batch)
//     blocks [1024,1232) k_u tile: 48m x 128n, 4m x 4n per thread
// ---------------------------------------------------------------------------
__global__ __launch_bounds__(384) void kB(const float* __restrict__ x0g) {
    __shared__ __align__(16) char smem_pool[37248];
    const int t = threadIdx.x;

    if (blockIdx.x >= FEATB) {
        // ---- k_u part ----
        float (*As)[52]  = reinterpret_cast<float(*)[52]>(smem_pool);
        float (*Bs)[132] = reinterpret_cast<float(*)[132]>(smem_pool + 6656);
        int ub = blockIdx.x - FEATB;     // 0..207
        int m0 = (ub & 7) * 48;
        int n0 = (ub >> 3) * 128;
        const int tx = t & 31, ty = t >> 5;

        ull acc[4][2];
#pragma unroll
        for (int r = 0; r < 4; r++) { acc[r][0] = 0ULL; acc[r][1] = 0ULL; }

        for (int kc = 0; kc < 128; kc += 32) {
            __syncthreads();
            {   // A: 48m x 32k transpose (rows m0..m0+47, in-bounds of 384-row W1s)
                int row = t >> 3, c4 = t & 7;
                float4 v = *reinterpret_cast<const float4*>(
                    g_W1s + (size_t)(m0 + row) * 128 + kc + 4 * c4);
                As[4 * c4 + 0][row] = v.x;
                As[4 * c4 + 1][row] = v.y;
                As[4 * c4 + 2][row] = v.z;
                As[4 * c4 + 3][row] = v.w;
            }
#pragma unroll
            for (int l = 0; l < 3; l++) {   // B: 32k x 128n
                int idx = t + 384 * l;
                if (idx < 1024) {
                    int row = idx >> 5, c4 = idx & 31;
                    *reinterpret_cast<float4*>(&Bs[row][4 * c4]) =
                        *reinterpret_cast<const float4*>(g_W2t + (size_t)(kc + row) * NJ + n0 + 4 * c4);
                }
            }
            __syncthreads();

#pragma unroll
            for (int kk = 0; kk < 32; kk++) {
                float4 a = *reinterpret_cast<const float4*>(&As[kk][4 * ty]);
                ulonglong2 w = *reinterpret_cast<const ulonglong2*>(&Bs[kk][4 * tx]);
                ull d;
                DUP2(d, a.x); FMA2(acc[0][0], w.x, d); FMA2(acc[0][1], w.y, d);
                DUP2(d, a.y); FMA2(acc[1][0], w.x, d); FMA2(acc[1][1], w.y, d);
                DUP2(d, a.z); FMA2(acc[2][0], w.x, d); FMA2(acc[2][1], w.y, d);
                DUP2(d, a.w); FMA2(acc[3][0], w.x, d); FMA2(acc[3][1], w.y, d);
            }
        }
#pragma unroll
        for (int r = 0; r < 4; r++) {
            int m = m0 + 4 * ty + r;
            if (m < 352) {
                float* dst = g_U + (size_t)m * NJ + n0 + 4 * tx;
                *reinterpret_cast<float2*>(dst)     = *reinterpret_cast<float2*>(&acc[r][0]);
                *reinterpret_cast<float2*>(dst + 2) = *reinterpret_cast<float2*>(&acc[r][1]);
            }
        }
        return;
    }

    // ---- feat part ----
    ull   (*xsr)[MF][18] = reinterpret_cast<ull(*)[MF][18]>(smem_pool);
    float (*sF)[FSTR]    = reinterpret_cast<float(*)[FSTR]>(smem_pool + 7488);
    const int b0 = blockIdx.x * 2;

    for (int idx = t; idx < 832; idx += 384) {
        int s = idx >= 416; int r = idx - 416 * s;
        int j = r >> 4, kp = r & 15;
        xsr[s][j][kp] = *reinterpret_cast<const ull*>(
            x0g + (size_t)(b0 + s) * (MF * KE) + j * KE + 2 * kp);
    }
    if (t < 2) { sF[t][351] = 32.0f; sF[t][3654] = 32.0f; }
    if (t < 114) { int s = t >= 57; sF[s][3655 + t - 57 * s] = 0.0f; }
    __syncthreads();

    if (t < 52) {   // sx
        int s = t >= 26; int j = t - 26 * s;
        ull s0 = 0, s1 = 0;
#pragma unroll
        for (int cc = 0; cc < 8; cc++) {
            ulonglong2 v = *reinterpret_cast<const ulonglong2*>(&xsr[s][j][2 * cc]);
            ADD2(s0, v.x); ADD2(s1, v.y);
        }
        ADD2(s0, s1);
        sF[s][3628 + j] = hadd2(s0);
    }

    const int w = t >> 5, lane = t & 31;
    const int s = w >= 6;
    const int wl = w - 6 * s;
    const int pqA = (wl * 32 + lane) * 2;
    const int pqB = pqA + 1;
    const bool vA = pqA < NPAIR, vB = pqB < NPAIR;
    const int mA = g_meta[pqA], mB = g_meta[pqB];
    const int pA = mA & 31, qA = (mA >> 5) & 31, rbA = mA >> 10;
    const int pB = mB & 31, qB = (mB >> 5) & 31, rbB = mB >> 10;

    ull xxA[16], xxB[16];
#pragma unroll
    for (int cc = 0; cc < 8; cc++) {
        ulonglong2 xp = *reinterpret_cast<const ulonglong2*>(&xsr[s][pA][2 * cc]);
        ulonglong2 xq = *reinterpret_cast<const ulonglong2*>(&xsr[s][qA][2 * cc]);
        MUL2(xxA[2 * cc],     xp.x, xq.x);
        MUL2(xxA[2 * cc + 1], xp.y, xq.y);
    }
#pragma unroll
    for (int cc = 0; cc < 8; cc++) {
        ulonglong2 xp = *reinterpret_cast<const ulonglong2*>(&xsr[s][pB][2 * cc]);
        ulonglong2 xq = *reinterpret_cast<const ulonglong2*>(&xsr[s][qB][2 * cc]);
        MUL2(xxB[2 * cc],     xp.x, xq.x);
        MUL2(xxB[2 * cc + 1], xp.y, xq.y);
    }

    {   // G
        ull g0 = 0, g1 = 0;
#pragma unroll
        for (int kp = 0; kp < 16; kp += 2) { ADD2(g0, xxA[kp]); ADD2(g1, xxA[kp + 1]); }
        ADD2(g0, g1);
        if (vA) sF[s][pqA] = hadd2(g0);
        ull h0 = 0, h1 = 0;
#pragma unroll
        for (int kp = 0; kp < 16; kp += 2) { ADD2(h0, xxB[kp]); ADD2(h1, xxB[kp + 1]); }
        ADD2(h0, h1);
        if (vB) sF[s][pqB] = hadd2(h0);
    }

    for (int j = 0; j < MF; j++) {
        ull a0 = 0, a1 = 0, c0 = 0, c1 = 0;
#pragma unroll
        for (int cc = 0; cc < 8; cc++) {
            ulonglong2 xj = *reinterpret_cast<const ulonglong2*>(&xsr[s][j][2 * cc]);
            FMA2(a0, xxA[2 * cc],     xj.x);
            FMA2(a1, xxA[2 * cc + 1], xj.y);
            FMA2(c0, xxB[2 * cc],     xj.x);
            FMA2(c1, xxB[2 * cc + 1], xj.y);
        }
        ADD2(a0, a1); ADD2(c0, c1);
        if (vA && j >= qA) sF[s][352 + rbA + j - qA] = hadd2(a0);
        if (vB && j >= qB) sF[s][352 + rbB + j - qB] = hadd2(c0);
    }
    __syncthreads();

    for (int idx = t; idx < 1856; idx += 384) {
        int s2 = idx >= 928; int r = idx - 928 * s2;
        *reinterpret_cast<float4*>(g_F + (size_t)(b0 + s2) * FSTR + 4 * r) =
            *reinterpret_cast<const float4*>(&sF[s2][4 * r]);
    }
}

// ---------------------------------------------------------------------------
// k_fold: Up rows: e<3276 permutation fold of U; 3276..3301 = U row 351 (v);
//         3302 = b2; 3303..3327 = 0.
// ---------------------------------------------------------------------------
__global__ void k_fold(const float* __restrict__ b2) {
    int gid = blockIdx.x * blockDim.x + threadIdx.x;   // 3328*128
    int e = gid >> 7, h = gid & 127;
    float val = 0.f;
    if (e < NTRI) {
        int c = g_e2pqj[e];
        int p = c & 255, q = (c >> 8) & 255, j = (c >> 16) & 255;
        #define CU(PQ, J) g_U[(size_t)(PQ) * NJ + (J) * 128 + h]
        if (p < q) {
            if (q < j) val = CU(pq_off(p) + q - p, j) + CU(pq_off(p) + j - p, q) + CU(pq_off(q) + j - q, p);
            else       val = CU(pq_off(p) + q - p, q) + CU(pq_off(q), p);
        } else {
            if (q < j) val = CU(pq_off(p), j) + CU(pq_off(p) + j - p, p);
            else       val = CU(pq_off(p), p);
        }
        #undef CU
    } else if (e < NTRI + MF) {
        val = g_U[(size_t)NPAIR * NJ + (e - NTRI) * 128 + h];   // v[j][h]
    } else if (e == NTRI + MF) {
        val = b2[h];
    }
    g_Up[(size_t)e * 128 + h] = val;
}

// ---------------------------------------------------------------------------
// gemm core: 64b x 128h tile, 256 thr, thread = 4 b-pairs x 4h (FMA-bound).
// ---------------------------------------------------------------------------
__device__ __forceinline__ void gemm_core(
    const float* __restrict__ Wrows,   // [k][128]
    const float* __restrict__ Frow,    // g_F + fbase (col offset applied)
    int nchunks, int b0,
    float* __restrict__ dst, int dstr,
    ull (*As2)[34], float (*Ws)[132])
{
    const int t  = threadIdx.x;
    const int hq = t & 31;
    const int bg = t >> 5;

    ull acc[4][4];
#pragma unroll
    for (int bp = 0; bp < 4; bp++)
#pragma unroll
        for (int e = 0; e < 4; e++) acc[bp][e] = 0ULL;

    for (int ch = 0; ch < nchunks; ch++) {
        int kc = ch * 32;
        __syncthreads();
#pragma unroll
        for (int l = 0; l < 2; l++) {   // A: 64b x 32k, pair-packed
            int idx = t + 256 * l;
            int row = idx >> 3, c4 = idx & 7;
            float4 v = *reinterpret_cast<const float4*>(
                Frow + (size_t)(b0 + row) * FSTR + kc + 4 * c4);
            int bp = row >> 1, lo = row & 1;
            reinterpret_cast<float*>(&As2[4 * c4 + 0][bp])[lo] = v.x;
            reinterpret_cast<float*>(&As2[4 * c4 + 1][bp])[lo] = v.y;
            reinterpret_cast<float*>(&As2[4 * c4 + 2][bp])[lo] = v.z;
            reinterpret_cast<float*>(&As2[4 * c4 + 3][bp])[lo] = v.w;
        }
#pragma unroll
        for (int l = 0; l < 4; l++) {   // W: 32k x 128h
            int idx = t + 256 * l;
            int row = idx >> 5, c4 = idx & 31;
            *reinterpret_cast<float4*>(&Ws[row][4 * c4]) =
                *reinterpret_cast<const float4*>(Wrows + (size_t)(kc + row) * 128 + 4 * c4);
        }
        __syncthreads();

#pragma unroll
        for (int kk = 0; kk < 32; kk++) {
            ulonglong2 aA = *reinterpret_cast<const ulonglong2*>(&As2[kk][4 * bg]);
            ulonglong2 aB = *reinterpret_cast<const ulonglong2*>(&As2[kk][4 * bg + 2]);
            float4 wv = *reinterpret_cast<const float4*>(&Ws[kk][4 * hq]);
            ull w0, w1, w2, w3;
            DUP2(w0, wv.x); DUP2(w1, wv.y); DUP2(w2, wv.z); DUP2(w3, wv.w);
            FMA2(acc[0][0], aA.x, w0); FMA2(acc[0][1], aA.x, w1);
            FMA2(acc[0][2], aA.x, w2); FMA2(acc[0][3], aA.x, w3);
            FMA2(acc[1][0], aA.y, w0); FMA2(acc[1][1], aA.y, w1);
            FMA2(acc[1][2], aA.y, w2); FMA2(acc[1][3], aA.y, w3);
            FMA2(acc[2][0], aB.x, w0); FMA2(acc[2][1], aB.x, w1);
            FMA2(acc[2][2], aB.x, w2); FMA2(acc[2][3], aB.x, w3);
            FMA2(acc[3][0], aB.y, w0); FMA2(acc[3][1], aB.y, w1);
            FMA2(acc[3][2], aB.y, w2); FMA2(acc[3][3], aB.y, w3);
        }
    }

#pragma unroll
    for (int bp = 0; bp < 4; bp++) {
        int b = b0 + 8 * bg + 2 * bp;
#pragma unroll
        for (int e = 0; e < 4; e++) {
            float2 v = *reinterpret_cast<float2*>(&acc[bp][e]);
            dst[(size_t)b * dstr + 4 * hq + e]       = v.x;
            dst[(size_t)(b + 1) * dstr + 4 * hq + e] = v.y;
        }
    }
}

// ---------------------------------------------------------------------------
// k_gemm: persistent, 148 blocks.
//   id<128: gemm1 tile (bt = id>>2, k-split ks = id&3) -> g_P[ks]
//   id>=128: gemm0 tiles (out cols 0..127), strided over 20 blocks
// ---------------------------------------------------------------------------
__global__ __launch_bounds__(256) void k_gemm(float* __restrict__ out) {
    __shared__ __align__(16) ull   As2[32][34];
    __shared__ __align__(16) float Ws[32][132];
    int id = blockIdx.x;
    if (id < 128) {
        int bt = id >> 2, ks = id & 3;
        gemm_core(g_Up + (size_t)(832 * ks) * 128,
                  g_F + 352 + 832 * ks,
                  26, 64 * bt,
                  g_P + (size_t)ks * BATCH * 128, 128, As2, Ws);
    } else {
        for (int tile = id - 128; tile < 32; tile += 20)
            gemm_core(g_W1s, g_F, 11, 64 * tile, out, OUTW, As2, Ws);
    }
}

// ---------------------------------------------------------------------------
// k_red: out[:,128:256] = sum of 4 partials
// ---------------------------------------------------------------------------
__global__ void k_red(float* __restrict__ out) {
    int gid = blockIdx.x * blockDim.x + threadIdx.x;   // 2048*128
    int b = gid >> 7, h = gid & 127;
    const int N = BATCH * 128;
    out[(size_t)b * OUTW + 128 + h] =
        (g_P[gid] + g_P[gid + N]) + (g_P[gid + 2 * N] + g_P[gid + 3 * N]);
}

// ---------------------------------------------------------------------------
extern "C" void kernel_launch(void* const* d_in, const int* in_sizes, int n_in,
                              void* d_out, int out_size) {
    const float* inputs = (const float*)d_in[0];  // [2048,26,32]
    const float* W1     = (const float*)d_in[1];  // [128,26,26]
    const float* b1     = (const float*)d_in[2];  // [128]
    const float* W2     = (const float*)d_in[3];  // [128,128,26]
    const float* b2     = (const float*)d_in[4];  // [128]
    float* out = (float*)d_out;                   // [2048,256]

    kA_prep<<<622, 256>>>(W1, b1, W2);
    kB<<<FEATB + 208, 384>>>(inputs);
    k_fold<<<(NJ * 128) / 256, 256>>>(b2);
    k_gemm<<<148, 256>>>(out);
    k_red<<<(BATCH * 128) / 256, 256>>>(out);
}

// round 7
// speedup vs baseline: 2.0055x; 1.1917x over previous
#include <cuda_runtime.h>

#define BATCH 2048
#define MF    26
#define KE    32
#define C1    (MF*MF)       // 676
#define NPAIR 351
#define NTRI  3276
#define NJ    3328          // 26*128
#define OUTW  256
#define FSTR  3712          // F row: [G 0..350 | 32@351 | T 352..3627 | sx 3628..3653 | 32@3654 | 0..3711]
#define FEATB 1024

typedef unsigned long long ull;

__device__ int   g_e2pqj[NTRI];          // p | q<<8 | j<<16  (i-major)
__device__ int   g_meta2[384];           // q-major entry -> p | q<<5 | rb<<10
__device__ float g_W1s[384 * 128];       // [pq][i]; row 351 = b1, rows 352..383 = 0
__device__ float g_W2t[NJ * 128];        // [i][j*128+h], i-row stride NJ
__device__ float g_U[352 * NJ];          // [pq][j*128+h]; row 351 = v[j][h]
__device__ float g_Up[NJ * 128];         // rows: 0..3275 fold, 3276..3301 v, 3302 b2, rest 0
__device__ float g_F[BATCH * FSTR];
__device__ float g_P[8 * BATCH * 128];   // gemm1 k-split partials

#define FMA2(a, x, y) asm("fma.rn.f32x2 %0, %1, %2, %0;" : "+l"(a) : "l"(x), "l"(y))
#define MUL2(d, x, y) asm("mul.rn.f32x2 %0, %1, %2;" : "=l"(d) : "l"(x), "l"(y))
#define ADD2(a, x)    asm("add.rn.f32x2 %0, %0, %1;" : "+l"(a) : "l"(x))
#define DUP2(d, f)    asm("mov.b64 %0, {%1, %1};" : "=l"(d) : "f"(f))

__device__ __forceinline__ int pq_off(int p) { return p * MF - (p * (p - 1)) / 2; }

__device__ __forceinline__ void pq_decode(int pq, int& p, int& q) {
    p = (int)(26.5f - sqrtf(702.25f - 2.0f * (float)pq));
    if (p < 0) p = 0;
    while (p > 0 && pq_off(p) > pq) p--;
    while (pq_off(p + 1) <= pq) p++;
    q = p + (pq - pq_off(p));
}

__device__ __forceinline__ float hadd2(ull a) {
    float2 f = *reinterpret_cast<float2*>(&a);
    return f.x + f.y;
}

// ---------------------------------------------------------------------------
// kA_prep: [0,416) W2 transpose; [416,608) W1s; [608,621) e2pqj; [621] meta2
// ---------------------------------------------------------------------------
__global__ __launch_bounds__(256) void kA_prep(
    const float* __restrict__ W1, const float* __restrict__ b1,
    const float* __restrict__ W2)
{
    const int bx = blockIdx.x;
    const int t  = threadIdx.x;
    if (bx < 416) {
        __shared__ float tile[32][33];
        int c0 = (bx % 104) * 32;
        int h0 = (bx / 104) * 32;
        int tx = t & 31, ty = t >> 5;
#pragma unroll
        for (int r = 0; r < 4; r++)
            tile[ty + 8 * r][tx] = W2[(size_t)(h0 + ty + 8 * r) * NJ + c0 + tx];
        __syncthreads();
#pragma unroll
        for (int r = 0; r < 4; r++)
            g_W2t[(size_t)(c0 + ty + 8 * r) * 128 + h0 + tx] = tile[tx][ty + 8 * r];
    } else if (bx < 608) {
        int idx = (bx - 416) * 256 + t;           // 384*128
        int pq = idx >> 7, i = idx & 127;
        float v = 0.f;
        if (pq == NPAIR) v = b1[i];
        else if (pq < NPAIR) {
            int p, q; pq_decode(pq, p, q);
            v = W1[i * C1 + p * MF + q];
            if (p < q) v += W1[i * C1 + q * MF + p];
        }
        g_W1s[idx] = v;
    } else if (bx < 621) {
        int e = (bx - 608) * 256 + t;
        if (e < NTRI) {
            int rem = e, p = 0;
            while (rem >= (MF - p) * (MF - p + 1) / 2) { rem -= (MF - p) * (MF - p + 1) / 2; p++; }
            int q = p;
            while (rem >= MF - q) { rem -= MF - q; q++; }
            g_e2pqj[e] = p | (q << 8) | ((q + rem) << 16);
        }
    } else {
        for (int eq = t; eq < 384; eq += 256) {   // q-major meta
            int v = 0;
            if (eq < NPAIR) {
                int q = 0;
                while ((q + 1) * (q + 2) / 2 <= eq) q++;
                int p = eq - q * (q + 1) / 2;
                int rb = 0;
                for (int pp = 0; pp < p; pp++) rb += (MF - pp) * (MF - pp + 1) / 2;
                rb += (MF - p) * (MF - p + 1) / 2 - (MF - q) * (MF - q + 1) / 2;
                v = p | (q << 5) | (rb << 10);
            }
            g_meta2[eq] = v;
        }
    }
}

// ---------------------------------------------------------------------------
// kB: [0,1024) feat (2 batches, 384 thr, q-major segments)
//     [1024,1232) k_u tiles 48m x 128n
// ---------------------------------------------------------------------------
__global__ __launch_bounds__(384) void kB(const float* __restrict__ x0g) {
    __shared__ __align__(16) char smem_pool[37248];
    const int t = threadIdx.x;

    if (blockIdx.x >= FEATB) {
        // ---- k_u ----
        float (*As)[52]  = reinterpret_cast<float(*)[52]>(smem_pool);
        float (*Bs)[132] = reinterpret_cast<float(*)[132]>(smem_pool + 6656);
        int ub = blockIdx.x - FEATB;
        int m0 = (ub & 7) * 48;
        int n0 = (ub >> 3) * 128;
        const int tx = t & 31, ty = t >> 5;

        ull acc[4][2];
#pragma unroll
        for (int r = 0; r < 4; r++) { acc[r][0] = 0ULL; acc[r][1] = 0ULL; }

        for (int kc = 0; kc < 128; kc += 32) {
            __syncthreads();
            {
                int row = t >> 3, c4 = t & 7;
                float4 v = *reinterpret_cast<const float4*>(
                    g_W1s + (size_t)(m0 + row) * 128 + kc + 4 * c4);
                As[4 * c4 + 0][row] = v.x;
                As[4 * c4 + 1][row] = v.y;
                As[4 * c4 + 2][row] = v.z;
                As[4 * c4 + 3][row] = v.w;
            }
#pragma unroll
            for (int l = 0; l < 3; l++) {
                int idx = t + 384 * l;
                if (idx < 1024) {
                    int row = idx >> 5, c4 = idx & 31;
                    *reinterpret_cast<float4*>(&Bs[row][4 * c4]) =
                        *reinterpret_cast<const float4*>(g_W2t + (size_t)(kc + row) * NJ + n0 + 4 * c4);
                }
            }
            __syncthreads();

#pragma unroll
            for (int kk = 0; kk < 32; kk++) {
                float4 a = *reinterpret_cast<const float4*>(&As[kk][4 * ty]);
                ulonglong2 w = *reinterpret_cast<const ulonglong2*>(&Bs[kk][4 * tx]);
                ull d;
                DUP2(d, a.x); FMA2(acc[0][0], w.x, d); FMA2(acc[0][1], w.y, d);
                DUP2(d, a.y); FMA2(acc[1][0], w.x, d); FMA2(acc[1][1], w.y, d);
                DUP2(d, a.z); FMA2(acc[2][0], w.x, d); FMA2(acc[2][1], w.y, d);
                DUP2(d, a.w); FMA2(acc[3][0], w.x, d); FMA2(acc[3][1], w.y, d);
            }
        }
#pragma unroll
        for (int r = 0; r < 4; r++) {
            int m = m0 + 4 * ty + r;
            if (m < 352) {
                float* dst = g_U + (size_t)m * NJ + n0 + 4 * tx;
                *reinterpret_cast<float2*>(dst)     = *reinterpret_cast<float2*>(&acc[r][0]);
                *reinterpret_cast<float2*>(dst + 2) = *reinterpret_cast<float2*>(&acc[r][1]);
            }
        }
        return;
    }

    // ---- feat ----
    ull   (*xsr)[MF][18] = reinterpret_cast<ull(*)[MF][18]>(smem_pool);
    float (*sF)[FSTR]    = reinterpret_cast<float(*)[FSTR]>(smem_pool + 7488);
    const int b0 = blockIdx.x * 2;

    for (int idx = t; idx < 832; idx += 384) {
        int s = idx >= 416; int r = idx - 416 * s;
        int j = r >> 4, kp = r & 15;
        xsr[s][j][kp] = *reinterpret_cast<const ull*>(
            x0g + (size_t)(b0 + s) * (MF * KE) + j * KE + 2 * kp);
    }
    if (t < 2) { sF[t][351] = 32.0f; sF[t][3654] = 32.0f; }
    if (t < 114) { int s = t >= 57; sF[s][3655 + t - 57 * s] = 0.0f; }
    __syncthreads();

    if (t < 52) {   // sx
        int s = t >= 26; int j = t - 26 * s;
        ull s0 = 0, s1 = 0;
#pragma unroll
        for (int cc = 0; cc < 8; cc++) {
            ulonglong2 v = *reinterpret_cast<const ulonglong2*>(&xsr[s][j][2 * cc]);
            ADD2(s0, v.x); ADD2(s1, v.y);
        }
        ADD2(s0, s1);
        sF[s][3628 + j] = hadd2(s0);
    }

    const int w = t >> 5, lane = t & 31;
    const int s   = w & 1;
    const int seg = (int)((0x335522441100ULL >> (4 * w)) & 15);
    const int js  = (seg == 0) ? 0 : (seg == 1) ? 10 : (seg == 2) ? 15
                  : (seg == 3) ? 19 : (seg == 4) ? 22 : 24;

    const int eqA = seg * 64 + 2 * lane;
    const int eqB = eqA + 1;
    const bool vA = eqA < NPAIR, vB = eqB < NPAIR;
    const int mA = g_meta2[eqA], mB = g_meta2[eqB];
    const int pA = mA & 31, qA = (mA >> 5) & 31, rbA = mA >> 10;
    const int pB = mB & 31, qB = (mB >> 5) & 31, rbB = mB >> 10;

    ull xxA[16], xxB[16];
#pragma unroll
    for (int cc = 0; cc < 8; cc++) {
        ulonglong2 xp = *reinterpret_cast<const ulonglong2*>(&xsr[s][pA][2 * cc]);
        ulonglong2 xq = *reinterpret_cast<const ulonglong2*>(&xsr[s][qA][2 * cc]);
        MUL2(xxA[2 * cc],     xp.x, xq.x);
        MUL2(xxA[2 * cc + 1], xp.y, xq.y);
    }
#pragma unroll
    for (int cc = 0; cc < 8; cc++) {
        ulonglong2 xp = *reinterpret_cast<const ulonglong2*>(&xsr[s][pB][2 * cc]);
        ulonglong2 xq = *reinterpret_cast<const ulonglong2*>(&xsr[s][qB][2 * cc]);
        MUL2(xxB[2 * cc],     xp.x, xq.x);
        MUL2(xxB[2 * cc + 1], xp.y, xq.y);
    }

    {   // G (store at i-major pq index)
        ull g0 = 0, g1 = 0;
#pragma unroll
        for (int kp = 0; kp < 16; kp += 2) { ADD2(g0, xxA[kp]); ADD2(g1, xxA[kp + 1]); }
        ADD2(g0, g1);
        if (vA) sF[s][pq_off(pA) + qA - pA] = hadd2(g0);
        ull h0 = 0, h1 = 0;
#pragma unroll
        for (int kp = 0; kp < 16; kp += 2) { ADD2(h0, xxB[kp]); ADD2(h1, xxB[kp + 1]); }
        ADD2(h0, h1);
        if (vB) sF[s][pq_off(pB) + qB - pB] = hadd2(h0);
    }

    for (int j = js; j < MF; j++) {
        ull a0 = 0, a1 = 0, c0 = 0, c1 = 0;
#pragma unroll
        for (int cc = 0; cc < 8; cc++) {
            ulonglong2 xj = *reinterpret_cast<const ulonglong2*>(&xsr[s][j][2 * cc]);
            FMA2(a0, xxA[2 * cc],     xj.x);
            FMA2(a1, xxA[2 * cc + 1], xj.y);
            FMA2(c0, xxB[2 * cc],     xj.x);
            FMA2(c1, xxB[2 * cc + 1], xj.y);
        }
        ADD2(a0, a1); ADD2(c0, c1);
        if (vA && j >= qA) sF[s][352 + rbA + j - qA] = hadd2(a0);
        if (vB && j >= qB) sF[s][352 + rbB + j - qB] = hadd2(c0);
    }
    __syncthreads();

    for (int idx = t; idx < 1856; idx += 384) {
        int s2 = idx >= 928; int r = idx - 928 * s2;
        *reinterpret_cast<float4*>(g_F + (size_t)(b0 + s2) * FSTR + 4 * r) =
            *reinterpret_cast<const float4*>(&sF[s2][4 * r]);
    }
}

// ---------------------------------------------------------------------------
// k_fold
// ---------------------------------------------------------------------------
__global__ void k_fold(const float* __restrict__ b2) {
    int gid = blockIdx.x * blockDim.x + threadIdx.x;   // 3328*128
    int e = gid >> 7, h = gid & 127;
    float val = 0.f;
    if (e < NTRI) {
        int c = g_e2pqj[e];
        int p = c & 255, q = (c >> 8) & 255, j = (c >> 16) & 255;
        #define CU(PQ, J) g_U[(size_t)(PQ) * NJ + (J) * 128 + h]
        if (p < q) {
            if (q < j) val = CU(pq_off(p) + q - p, j) + CU(pq_off(p) + j - p, q) + CU(pq_off(q) + j - q, p);
            else       val = CU(pq_off(p) + q - p, q) + CU(pq_off(q), p);
        } else {
            if (q < j) val = CU(pq_off(p), j) + CU(pq_off(p) + j - p, p);
            else       val = CU(pq_off(p), p);
        }
        #undef CU
    } else if (e < NTRI + MF) {
        val = g_U[(size_t)NPAIR * NJ + (e - NTRI) * 128 + h];
    } else if (e == NTRI + MF) {
        val = b2[h];
    }
    g_Up[(size_t)e * 128 + h] = val;
}

// ---------------------------------------------------------------------------
// gemm core: 64b x 128h, 256 thr, reg-buffered software pipeline.
// ---------------------------------------------------------------------------
__device__ __forceinline__ void gemm_core(
    const float* __restrict__ Wrows,
    const float* __restrict__ Frow,
    int nchunks, int b0,
    float* __restrict__ dst, int dstr,
    ull (*As2)[34], float (*Ws)[132])
{
    const int t  = threadIdx.x;
    const int hq = t & 31;
    const int bg = t >> 5;

    ull acc[4][4];
#pragma unroll
    for (int bp = 0; bp < 4; bp++)
#pragma unroll
        for (int e = 0; e < 4; e++) acc[bp][e] = 0ULL;

    float4 pa[2], pw[4];
    // prologue loads (chunk 0)
#pragma unroll
    for (int l = 0; l < 2; l++) {
        int idx = t + 256 * l, row = idx >> 3, c4 = idx & 7;
        pa[l] = *reinterpret_cast<const float4*>(Frow + (size_t)(b0 + row) * FSTR + 4 * c4);
    }
#pragma unroll
    for (int l = 0; l < 4; l++) {
        int idx = t + 256 * l, row = idx >> 5, c4 = idx & 31;
        pw[l] = *reinterpret_cast<const float4*>(Wrows + (size_t)row * 128 + 4 * c4);
    }

    for (int ch = 0; ch < nchunks; ch++) {
        // STS staged chunk
#pragma unroll
        for (int l = 0; l < 2; l++) {
            int idx = t + 256 * l, row = idx >> 3, c4 = idx & 7;
            int bp = row >> 1, lo = row & 1;
            reinterpret_cast<float*>(&As2[4 * c4 + 0][bp])[lo] = pa[l].x;
            reinterpret_cast<float*>(&As2[4 * c4 + 1][bp])[lo] = pa[l].y;
            reinterpret_cast<float*>(&As2[4 * c4 + 2][bp])[lo] = pa[l].z;
            reinterpret_cast<float*>(&As2[4 * c4 + 3][bp])[lo] = pa[l].w;
        }
#pragma unroll
        for (int l = 0; l < 4; l++) {
            int idx = t + 256 * l, row = idx >> 5, c4 = idx & 31;
            *reinterpret_cast<float4*>(&Ws[row][4 * c4]) = pw[l];
        }
        __syncthreads();

        // prefetch next chunk
        if (ch + 1 < nchunks) {
            int kc = (ch + 1) * 32;
#pragma unroll
            for (int l = 0; l < 2; l++) {
                int idx = t + 256 * l, row = idx >> 3, c4 = idx & 7;
                pa[l] = *reinterpret_cast<const float4*>(
                    Frow + (size_t)(b0 + row) * FSTR + kc + 4 * c4);
            }
#pragma unroll
            for (int l = 0; l < 4; l++) {
                int idx = t + 256 * l, row = idx >> 5, c4 = idx & 31;
                pw[l] = *reinterpret_cast<const float4*>(
                    Wrows + (size_t)(kc + row) * 128 + 4 * c4);
            }
        }

#pragma unroll
        for (int kk = 0; kk < 32; kk++) {
            ulonglong2 aA = *reinterpret_cast<const ulonglong2*>(&As2[kk][4 * bg]);
            ulonglong2 aB = *reinterpret_cast<const ulonglong2*>(&As2[kk][4 * bg + 2]);
            float4 wv = *reinterpret_cast<const float4*>(&Ws[kk][4 * hq]);
            ull w0, w1, w2, w3;
            DUP2(w0, wv.x); DUP2(w1, wv.y); DUP2(w2, wv.z); DUP2(w3, wv.w);
            FMA2(acc[0][0], aA.x, w0); FMA2(acc[0][1], aA.x, w1);
            FMA2(acc[0][2], aA.x, w2); FMA2(acc[0][3], aA.x, w3);
            FMA2(acc[1][0], aA.y, w0); FMA2(acc[1][1], aA.y, w1);
            FMA2(acc[1][2], aA.y, w2); FMA2(acc[1][3], aA.y, w3);
            FMA2(acc[2][0], aB.x, w0); FMA2(acc[2][1], aB.x, w1);
            FMA2(acc[2][2], aB.x, w2); FMA2(acc[2][3], aB.x, w3);
            FMA2(acc[3][0], aB.y, w0); FMA2(acc[3][1], aB.y, w1);
            FMA2(acc[3][2], aB.y, w2); FMA2(acc[3][3], aB.y, w3);
        }
        __syncthreads();
    }

#pragma unroll
    for (int bp = 0; bp < 4; bp++) {
        int b = b0 + 8 * bg + 2 * bp;
#pragma unroll
        for (int e = 0; e < 4; e++) {
            float2 v = *reinterpret_cast<float2*>(&acc[bp][e]);
            dst[(size_t)b * dstr + 4 * hq + e]       = v.x;
            dst[(size_t)(b + 1) * dstr + 4 * hq + e] = v.y;
        }
    }
}

// ---------------------------------------------------------------------------
// k_gemm: grid 296, 2 CTAs/SM.
//   id<256: gemm1 tile (bt=id>>3, ks=id&7, 416 k each) -> g_P[ks]
//   id>=256: gemm0 tiles, strided
// ---------------------------------------------------------------------------
__global__ __launch_bounds__(256, 2) void k_gemm(float* __restrict__ out) {
    __shared__ __align__(16) ull   As2[32][34];
    __shared__ __align__(16) float Ws[32][132];
    int id = blockIdx.x;
    if (id < 256) {
        int bt = id >> 3, ks = id & 7;
        gemm_core(g_Up + (size_t)(416 * ks) * 128,
                  g_F + 352 + 416 * ks,
                  13, 64 * bt,
                  g_P + (size_t)ks * BATCH * 128, 128, As2, Ws);
    } else {
        for (int tile = id - 256; tile < 32; tile += 40)
            gemm_core(g_W1s, g_F, 11, 64 * tile, out, OUTW, As2, Ws);
    }
}

// ---------------------------------------------------------------------------
// k_red: out[:,128:256] = sum of 8 partials
// ---------------------------------------------------------------------------
__global__ void k_red(float* __restrict__ out) {
    int gid = blockIdx.x * blockDim.x + threadIdx.x;   // 2048*128
    int b = gid >> 7, h = gid & 127;
    const int N = BATCH * 128;
    float v = ((g_P[gid] + g_P[gid + N]) + (g_P[gid + 2 * N] + g_P[gid + 3 * N]))
            + ((g_P[gid + 4 * N] + g_P[gid + 5 * N]) + (g_P[gid + 6 * N] + g_P[gid + 7 * N]));
    out[(size_t)b * OUTW + 128 + h] = v;
}

// ---------------------------------------------------------------------------
extern "C" void kernel_launch(void* const* d_in, const int* in_sizes, int n_in,
                              void* d_out, int out_size) {
    const float* inputs = (const float*)d_in[0];
    const float* W1     = (const float*)d_in[1];
    const float* b1     = (const float*)d_in[2];
    const float* W2     = (const float*)d_in[3];
    const float* b2     = (const float*)d_in[4];
    float* out = (float*)d_out;

    kA_prep<<<622, 256>>>(W1, b1, W2);
    kB<<<FEATB + 208, 384>>>(inputs);
    k_fold<<<(NJ * 128) / 256, 256>>>(b2);
    k_gemm<<<296, 256>>>(out);
    k_red<<<(BATCH * 128) / 256, 256>>>(out);
}